// round 7
// baseline (speedup 1.0000x reference)
#include <cuda_runtime.h>
#include <cuda_fp16.h>
#include <math.h>

// Problem constants (fixed by the dataset)
#define NN    100000
#define EMAX  1600000
#define E2MAX 3200000   // 2 * EMAX
#define DIN   192
#define HH    64
#define DOUTT 32
#define CC    2
#define GG    256

// Scratch (static device arrays -- no allocation allowed)
__device__ __align__(16) float  g_h  [NN * HH];   // node features (fp32)
__device__ __align__(16) __half g_hwh[NN * HH];   // h @ W, fp16 gather payload
__device__ float g_dis[NN];          // deg^{-1/2}
__device__ int   g_deg[NN];          // degree (no self-loop)
__device__ int   g_rowstart[NN + 1]; // CSR row offsets
__device__ __align__(16) int2 g_rank[EMAX];  // (rank in src list, rank in dst list)
__device__ __align__(16) int2 g_adjc[E2MAX]; // (neighbor, coef bits)
__device__ __align__(16) float g_pool[GG * HH];
__device__ float g_cnt [GG];

__device__ __forceinline__ void red_add_v4(float4* addr, float a, float b,
                                           float c, float d) {
    asm volatile("red.global.add.v4.f32 [%0], {%1, %2, %3, %4};"
                 :: "l"(addr), "f"(a), "f"(b), "f"(c), "f"(d)
                 : "memory");
}

// ---------------------------------------------------------------------------
__global__ void k_init() {
    int i = blockIdx.x * blockDim.x + threadIdx.x;
    if (i < NN) g_deg[i] = 0;
    if (i < GG * HH) g_pool[i] = 0.0f;
    if (i < GG) g_cnt[i] = 0.0f;
}

// Degree histogram; keep the returned rank so the fill pass needs no atomics.
__global__ void k_degree(const int* __restrict__ src,
                         const int* __restrict__ dst, int E) {
    int i = blockIdx.x * blockDim.x + threadIdx.x;
    if (i >= E) return;
    int s = src[i], d = dst[i];
    int rs = atomicAdd(&g_deg[s], 1);
    int rd = atomicAdd(&g_deg[d], 1);
    g_rank[i] = make_int2(rs, rd);
}

// Exclusive scan of degrees -> rowstart, plus dis.
#define SCAN_T 1024
__global__ void k_scan(int N) {
    __shared__ int sums[SCAN_T];
    int t = threadIdx.x;
    int chunk = (N + SCAN_T - 1) / SCAN_T;
    int beg = t * chunk;
    int end = min(beg + chunk, N);
    int s = 0;
    for (int i = beg; i < end; i++) s += g_deg[i];
    sums[t] = s;
    __syncthreads();
    if (t == 0) {
        int run = 0;
        for (int u = 0; u < SCAN_T; u++) {
            int v = sums[u];
            sums[u] = run;       // exclusive prefix
            run += v;
        }
        g_rowstart[N] = run;     // total = 2E
    }
    __syncthreads();
    int run = sums[t];
    for (int i = beg; i < end; i++) {
        int d = g_deg[i];
        g_rowstart[i] = run;
        g_dis[i] = rsqrtf((float)d + 1.0f);
        run += d;
    }
}

// CSR fill, atomic-free: slot = rowstart[node] + precomputed rank.
__global__ void k_fill_adj(const int* __restrict__ src,
                           const int* __restrict__ dst, int E) {
    int i = blockIdx.x * blockDim.x + threadIdx.x;
    if (i >= E) return;
    int s = src[i], d = dst[i];
    int2 r = g_rank[i];
    float c = g_dis[s] * g_dis[d];
    int ci = __float_as_int(c);
    g_adjc[g_rowstart[s] + r.x] = make_int2(d, ci);
    g_adjc[g_rowstart[d] + r.y] = make_int2(s, ci);
}

// ---------------------------------------------------------------------------
// Write one row-chunk of 8 fp32 values as 8 fp16 (one uint4) to g_hwh.
__device__ __forceinline__ void store_h8(int row, int tc, const float* v) {
    __half2 h0 = __floats2half2_rn(v[0], v[1]);
    __half2 h1 = __floats2half2_rn(v[2], v[3]);
    __half2 h2 = __floats2half2_rn(v[4], v[5]);
    __half2 h3 = __floats2half2_rn(v[6], v[7]);
    uint4 u;
    u.x = *(unsigned*)&h0;
    u.y = *(unsigned*)&h1;
    u.z = *(unsigned*)&h2;
    u.w = *(unsigned*)&h3;
    ((uint4*)g_hwh)[row * 8 + tc] = u;
}

// ---------------------------------------------------------------------------
// Fused: g_hwh = fp16( relu(x @ W_in + b_in) @ W1 ).  h never hits gmem.
// Block tile 128 rows, 128 threads, 8x8 register tile, BK=16.
__global__ void k_gemm_fused(const float* __restrict__ x,
                             const float* __restrict__ W,
                             const float* __restrict__ bias,
                             const float* __restrict__ W1, int N) {
    __shared__ float As[16][128];
    __shared__ float Ws[16][64];
    __shared__ float Hs[64][128];   // transposed h tile: Hs[feat][row]
    int t  = threadIdx.x;
    int tr = t >> 3;                // 0..15
    int tc = t & 7;                 // 0..7
    int row0 = blockIdx.x * 128;

    float acc[8][8];
    #pragma unroll
    for (int i = 0; i < 8; i++)
        #pragma unroll
        for (int j = 0; j < 8; j++) acc[i][j] = 0.0f;

    // ---- GEMM 1: x[128 x 192] @ W_in[192 x 64] ----
    for (int kt = 0; kt < DIN; kt += 16) {
        {
            int gr = row0 + t;
            float4 v0, v1, v2, v3;
            if (gr < N) {
                const float4* Ar = (const float4*)(x + (long)gr * DIN + kt);
                v0 = Ar[0]; v1 = Ar[1]; v2 = Ar[2]; v3 = Ar[3];
            } else {
                v0 = make_float4(0.f,0.f,0.f,0.f); v1 = v0; v2 = v0; v3 = v0;
            }
            As[ 0][t] = v0.x; As[ 1][t] = v0.y; As[ 2][t] = v0.z; As[ 3][t] = v0.w;
            As[ 4][t] = v1.x; As[ 5][t] = v1.y; As[ 6][t] = v1.z; As[ 7][t] = v1.w;
            As[ 8][t] = v2.x; As[ 9][t] = v2.y; As[10][t] = v2.z; As[11][t] = v2.w;
            As[12][t] = v3.x; As[13][t] = v3.y; As[14][t] = v3.z; As[15][t] = v3.w;
        }
        {
            const float4* Wg = (const float4*)(W + kt * 64);
            ((float4*)Ws)[t]       = Wg[t];
            ((float4*)Ws)[t + 128] = Wg[t + 128];
        }
        __syncthreads();
        #pragma unroll
        for (int k = 0; k < 16; k++) {
            float4 a0 = *(const float4*)&As[k][tr * 8];
            float4 a1 = *(const float4*)&As[k][tr * 8 + 4];
            float4 b0 = *(const float4*)&Ws[k][tc * 8];
            float4 b1 = *(const float4*)&Ws[k][tc * 8 + 4];
            float a[8], b[8];
            a[0]=a0.x; a[1]=a0.y; a[2]=a0.z; a[3]=a0.w;
            a[4]=a1.x; a[5]=a1.y; a[6]=a1.z; a[7]=a1.w;
            b[0]=b0.x; b[1]=b0.y; b[2]=b0.z; b[3]=b0.w;
            b[4]=b1.x; b[5]=b1.y; b[6]=b1.z; b[7]=b1.w;
            #pragma unroll
            for (int i = 0; i < 8; i++)
                #pragma unroll
                for (int j = 0; j < 8; j++)
                    acc[i][j] = fmaf(a[i], b[j], acc[i][j]);
        }
        __syncthreads();
    }

    // Epilogue 1: h = relu(acc + bias), transposed into Hs[feat][row].
    {
        float4 bb0 = ((const float4*)bias)[tc * 2];
        float4 bb1 = ((const float4*)bias)[tc * 2 + 1];
        float bv[8];
        bv[0]=bb0.x; bv[1]=bb0.y; bv[2]=bb0.z; bv[3]=bb0.w;
        bv[4]=bb1.x; bv[5]=bb1.y; bv[6]=bb1.z; bv[7]=bb1.w;
        #pragma unroll
        for (int i = 0; i < 8; i++)
            #pragma unroll
            for (int j = 0; j < 8; j++)
                Hs[tc * 8 + j][tr * 8 + i] = fmaxf(acc[i][j] + bv[j], 0.0f);
    }
    __syncthreads();

    // ---- GEMM 2: h[128 x 64] @ W1[64 x 64] ----
    #pragma unroll
    for (int i = 0; i < 8; i++)
        #pragma unroll
        for (int j = 0; j < 8; j++) acc[i][j] = 0.0f;

    for (int kt = 0; kt < HH; kt += 16) {
        {
            const float4* Wg = (const float4*)(W1 + kt * 64);
            ((float4*)Ws)[t]       = Wg[t];
            ((float4*)Ws)[t + 128] = Wg[t + 128];
        }
        __syncthreads();
        #pragma unroll
        for (int k = 0; k < 16; k++) {
            float4 a0 = *(const float4*)&Hs[kt + k][tr * 8];
            float4 a1 = *(const float4*)&Hs[kt + k][tr * 8 + 4];
            float4 b0 = *(const float4*)&Ws[k][tc * 8];
            float4 b1 = *(const float4*)&Ws[k][tc * 8 + 4];
            float a[8], b[8];
            a[0]=a0.x; a[1]=a0.y; a[2]=a0.z; a[3]=a0.w;
            a[4]=a1.x; a[5]=a1.y; a[6]=a1.z; a[7]=a1.w;
            b[0]=b0.x; b[1]=b0.y; b[2]=b0.z; b[3]=b0.w;
            b[4]=b1.x; b[5]=b1.y; b[6]=b1.z; b[7]=b1.w;
            #pragma unroll
            for (int i = 0; i < 8; i++)
                #pragma unroll
                for (int j = 0; j < 8; j++)
                    acc[i][j] = fmaf(a[i], b[j], acc[i][j]);
        }
        __syncthreads();
    }

    #pragma unroll
    for (int i = 0; i < 8; i++) {
        int gr = row0 + tr * 8 + i;
        if (gr < N) store_h8(gr, tc, acc[i]);
    }
}

// g_hwh = fp16( g_h @ W2 ). Same register-tiled structure.
__global__ void k_gemm2(const float* __restrict__ W, int N) {
    __shared__ float As[16][128];
    __shared__ float Ws[16][64];
    int t  = threadIdx.x;
    int tr = t >> 3;
    int tc = t & 7;
    int row0 = blockIdx.x * 128;

    float acc[8][8];
    #pragma unroll
    for (int i = 0; i < 8; i++)
        #pragma unroll
        for (int j = 0; j < 8; j++) acc[i][j] = 0.0f;

    for (int kt = 0; kt < HH; kt += 16) {
        {
            int gr = row0 + t;
            float4 v0, v1, v2, v3;
            if (gr < N) {
                const float4* Ar = (const float4*)(g_h + (long)gr * HH + kt);
                v0 = Ar[0]; v1 = Ar[1]; v2 = Ar[2]; v3 = Ar[3];
            } else {
                v0 = make_float4(0.f,0.f,0.f,0.f); v1 = v0; v2 = v0; v3 = v0;
            }
            As[ 0][t] = v0.x; As[ 1][t] = v0.y; As[ 2][t] = v0.z; As[ 3][t] = v0.w;
            As[ 4][t] = v1.x; As[ 5][t] = v1.y; As[ 6][t] = v1.z; As[ 7][t] = v1.w;
            As[ 8][t] = v2.x; As[ 9][t] = v2.y; As[10][t] = v2.z; As[11][t] = v2.w;
            As[12][t] = v3.x; As[13][t] = v3.y; As[14][t] = v3.z; As[15][t] = v3.w;
        }
        {
            const float4* Wg = (const float4*)(W + kt * 64);
            ((float4*)Ws)[t]       = Wg[t];
            ((float4*)Ws)[t + 128] = Wg[t + 128];
        }
        __syncthreads();
        #pragma unroll
        for (int k = 0; k < 16; k++) {
            float4 a0 = *(const float4*)&As[k][tr * 8];
            float4 a1 = *(const float4*)&As[k][tr * 8 + 4];
            float4 b0 = *(const float4*)&Ws[k][tc * 8];
            float4 b1 = *(const float4*)&Ws[k][tc * 8 + 4];
            float a[8], b[8];
            a[0]=a0.x; a[1]=a0.y; a[2]=a0.z; a[3]=a0.w;
            a[4]=a1.x; a[5]=a1.y; a[6]=a1.z; a[7]=a1.w;
            b[0]=b0.x; b[1]=b0.y; b[2]=b0.z; b[3]=b0.w;
            b[4]=b1.x; b[5]=b1.y; b[6]=b1.z; b[7]=b1.w;
            #pragma unroll
            for (int i = 0; i < 8; i++)
                #pragma unroll
                for (int j = 0; j < 8; j++)
                    acc[i][j] = fmaf(a[i], b[j], acc[i][j]);
        }
        __syncthreads();
    }

    #pragma unroll
    for (int i = 0; i < 8; i++) {
        int gr = row0 + tr * 8 + i;
        if (gr < N) store_h8(gr, tc, acc[i]);
    }
}

// ---------------------------------------------------------------------------
// Pull-based aggregation on fp16 payload: 8 lanes per node, each lane owns
// 8 features (16B per neighbor load -> one 128B line per neighbor per node).
// POOL=false: g_h[n] = relu(agg + b)   (fp32)
// POOL=true : red_add relu(agg + b) into g_pool[batch[n]].
__device__ __forceinline__ void acc_h8(float* acc, uint4 u, float c) {
    __half2 h0 = *(__half2*)&u.x;
    __half2 h1 = *(__half2*)&u.y;
    __half2 h2 = *(__half2*)&u.z;
    __half2 h3 = *(__half2*)&u.w;
    float2 f0 = __half22float2(h0);
    float2 f1 = __half22float2(h1);
    float2 f2 = __half22float2(h2);
    float2 f3 = __half22float2(h3);
    acc[0] = fmaf(f0.x, c, acc[0]); acc[1] = fmaf(f0.y, c, acc[1]);
    acc[2] = fmaf(f1.x, c, acc[2]); acc[3] = fmaf(f1.y, c, acc[3]);
    acc[4] = fmaf(f2.x, c, acc[4]); acc[5] = fmaf(f2.y, c, acc[5]);
    acc[6] = fmaf(f3.x, c, acc[6]); acc[7] = fmaf(f3.y, c, acc[7]);
}

template<bool POOL>
__global__ void k_aggregate(const float* __restrict__ b,
                            const int* __restrict__ batch, int N) {
    int n = blockIdx.x * 32 + (threadIdx.x >> 3);
    int q = threadIdx.x & 7;          // feature group: [q*8, q*8+8)
    if (n >= N) return;
    const uint4* hwh = (const uint4*)g_hwh;
    float dn = g_dis[n];
    float dn2 = dn * dn;
    float acc[8];
    {
        uint4 u = hwh[n * 8 + q];
        #pragma unroll
        for (int j = 0; j < 8; j++) acc[j] = 0.0f;
        acc_h8(acc, u, dn2);
    }
    int s = g_rowstart[n];
    int e = g_rowstart[n + 1];
    int i = s;
    for (; i + 4 <= e; i += 4) {
        int2 a0 = g_adjc[i];
        int2 a1 = g_adjc[i + 1];
        int2 a2 = g_adjc[i + 2];
        int2 a3 = g_adjc[i + 3];
        uint4 u0 = hwh[a0.x * 8 + q];
        uint4 u1 = hwh[a1.x * 8 + q];
        uint4 u2 = hwh[a2.x * 8 + q];
        uint4 u3 = hwh[a3.x * 8 + q];
        acc_h8(acc, u0, __int_as_float(a0.y));
        acc_h8(acc, u1, __int_as_float(a1.y));
        acc_h8(acc, u2, __int_as_float(a2.y));
        acc_h8(acc, u3, __int_as_float(a3.y));
    }
    for (; i < e; i++) {
        int2 a0 = g_adjc[i];
        uint4 u0 = hwh[a0.x * 8 + q];
        acc_h8(acc, u0, __int_as_float(a0.y));
    }

    float4 bb0 = ((const float4*)b)[q * 2];
    float4 bb1 = ((const float4*)b)[q * 2 + 1];
    float4 o0, o1;
    o0.x = fmaxf(acc[0] + bb0.x, 0.0f);
    o0.y = fmaxf(acc[1] + bb0.y, 0.0f);
    o0.z = fmaxf(acc[2] + bb0.z, 0.0f);
    o0.w = fmaxf(acc[3] + bb0.w, 0.0f);
    o1.x = fmaxf(acc[4] + bb1.x, 0.0f);
    o1.y = fmaxf(acc[5] + bb1.y, 0.0f);
    o1.z = fmaxf(acc[6] + bb1.z, 0.0f);
    o1.w = fmaxf(acc[7] + bb1.w, 0.0f);

    if (POOL) {
        int g = batch[n];
        float4* pool4 = (float4*)g_pool;
        red_add_v4(&pool4[g * 16 + q * 2],     o0.x, o0.y, o0.z, o0.w);
        red_add_v4(&pool4[g * 16 + q * 2 + 1], o1.x, o1.y, o1.z, o1.w);
        if (q == 0) atomicAdd(&g_cnt[g], 1.0f);
    } else {
        float4* h4 = (float4*)g_h;
        h4[n * 16 + q * 2]     = o0;
        h4[n * 16 + q * 2 + 1] = o1;
    }
}

// ---------------------------------------------------------------------------
__global__ void k_head(const float* __restrict__ Wf1,
                       const float* __restrict__ bf1,
                       const float* __restrict__ Wf2,
                       const float* __restrict__ bf2,
                       float* __restrict__ out) {
    __shared__ float W1s[HH * DOUTT];
    __shared__ float b1s[DOUTT];
    __shared__ float W2s[DOUTT * CC];
    __shared__ float b2s[CC];
    for (int i = threadIdx.x; i < HH * DOUTT; i += blockDim.x) W1s[i] = Wf1[i];
    if (threadIdx.x < DOUTT) b1s[threadIdx.x] = bf1[threadIdx.x];
    if (threadIdx.x < DOUTT * CC) W2s[threadIdx.x] = Wf2[threadIdx.x];
    if (threadIdx.x < CC) b2s[threadIdx.x] = bf2[threadIdx.x];
    __syncthreads();
    int g = threadIdx.x;
    if (g >= GG) return;
    float inv = 1.0f / fmaxf(g_cnt[g], 1.0f);
    float m[HH];
    #pragma unroll
    for (int k = 0; k < HH; k++) m[k] = g_pool[g * HH + k] * inv;
    float o0 = b2s[0], o1 = b2s[1];
    #pragma unroll
    for (int j = 0; j < DOUTT; j++) {
        float a = b1s[j];
        #pragma unroll
        for (int k = 0; k < HH; k++) a = fmaf(m[k], W1s[k * DOUTT + j], a);
        a = fmaxf(a, 0.0f);
        o0 = fmaf(a, W2s[j * CC + 0], o0);
        o1 = fmaf(a, W2s[j * CC + 1], o1);
    }
    float mx = fmaxf(o0, o1);
    float l = mx + logf(expf(o0 - mx) + expf(o1 - mx));
    out[g * CC + 0] = o0 - l;
    out[g * CC + 1] = o1 - l;
}

// ---------------------------------------------------------------------------
extern "C" void kernel_launch(void* const* d_in, const int* in_sizes, int n_in,
                              void* d_out, int out_size) {
    const float* x     = (const float*)d_in[0];
    const int*   ei    = (const int*)d_in[1];
    const int*   batch = (const int*)d_in[2];
    int idx = (n_in >= 14 && in_sizes[3] == 1) ? 4 : 3;
    const float* W_in = (const float*)d_in[idx++];
    const float* b_in = (const float*)d_in[idx++];
    const float* W1   = (const float*)d_in[idx++];
    const float* b1   = (const float*)d_in[idx++];
    const float* W2   = (const float*)d_in[idx++];
    const float* b2   = (const float*)d_in[idx++];
    const float* Wf1  = (const float*)d_in[idx++];
    const float* bf1  = (const float*)d_in[idx++];
    const float* Wf2  = (const float*)d_in[idx++];
    const float* bf2  = (const float*)d_in[idx++];

    int N = in_sizes[0] / DIN;
    int E = in_sizes[1] / 2;
    const int* src = ei;
    const int* dst = ei + E;

    // One-time stream/event setup.
    static cudaStream_t sB = nullptr;
    static cudaEvent_t evFork = nullptr, evJoin = nullptr;
    if (sB == nullptr) {
        cudaStreamCreateWithFlags(&sB, cudaStreamNonBlocking);
        cudaEventCreateWithFlags(&evFork, cudaEventDisableTiming);
        cudaEventCreateWithFlags(&evJoin, cudaEventDisableTiming);
    }

    // Fork: CSR build on side stream, GEMM chain on main stream.
    cudaEventRecord(evFork, 0);
    cudaStreamWaitEvent(sB, evFork, 0);

    // --- side stream: CSR build ---
    k_init<<<(NN + 255) / 256, 256, 0, sB>>>();
    k_degree<<<(E + 255) / 256, 256, 0, sB>>>(src, dst, E);
    k_scan<<<1, SCAN_T, 0, sB>>>(N);
    k_fill_adj<<<(E + 255) / 256, 256, 0, sB>>>(src, dst, E);
    cudaEventRecord(evJoin, sB);

    int gblocks = (N + 127) / 128;

    // --- main stream: g_hwh = fp16( relu(x @ W_in + b_in) @ W1 ) ---
    k_gemm_fused<<<gblocks, 128>>>(x, W_in, b_in, W1, N);

    // Join: aggregation needs both CSR and g_hwh.
    cudaStreamWaitEvent(0, evJoin, 0);

    // conv 1 aggregate -> g_h (fp32)
    k_aggregate<false><<<(N + 31) / 32, 256>>>(b1, nullptr, N);

    // conv 2
    k_gemm2<<<gblocks, 128>>>(W2, N);
    // conv 2 aggregate fused with mean-pool accumulation
    k_aggregate<true><<<(N + 31) / 32, 256>>>(b2, batch, N);

    // head
    k_head<<<1, 256>>>(Wf1, bf1, Wf2, bf2, (float*)d_out);
}

// round 8
// speedup vs baseline: 1.3373x; 1.3373x over previous
#include <cuda_runtime.h>
#include <math.h>

// Problem constants (fixed by the dataset)
#define NN    100000
#define EMAX  1600000
#define E2MAX 3200000   // 2 * EMAX
#define DIN   192
#define HH    64
#define DOUTT 32
#define CC    2
#define GG    256

// Scratch (static device arrays -- no allocation allowed)
__device__ __align__(16) float g_h  [NN * HH];   // node features
__device__ __align__(16) float g_hw [NN * HH];   // h @ W (pre-aggregation)
__device__ float g_dis[NN];          // deg^{-1/2}
__device__ int   g_deg[NN];          // degree (no self-loop)
__device__ int   g_rowstart[NN + 1]; // CSR row offsets
__device__ __align__(16) int2 g_rank[EMAX];  // (rank in src list, rank in dst list)
__device__ __align__(16) long long g_adjc[E2MAX]; // lo: neighbor, hi: coef bits
__device__ __align__(16) float g_pool[GG * HH];
__device__ float g_cnt [GG];

__device__ __forceinline__ void red_add_v4(float4* addr, float a, float b,
                                           float c, float d) {
    asm volatile("red.global.add.v4.f32 [%0], {%1, %2, %3, %4};"
                 :: "l"(addr), "f"(a), "f"(b), "f"(c), "f"(d)
                 : "memory");
}

// ---------------------------------------------------------------------------
__global__ void k_init() {
    int i = blockIdx.x * blockDim.x + threadIdx.x;
    if (i < NN) g_deg[i] = 0;
    if (i < GG * HH) g_pool[i] = 0.0f;
    if (i < GG) g_cnt[i] = 0.0f;
}

// Degree histogram; keep the returned rank so the fill pass needs no atomics.
__global__ void k_degree(const int* __restrict__ src,
                         const int* __restrict__ dst, int E) {
    int i = blockIdx.x * blockDim.x + threadIdx.x;
    if (i >= E) return;
    int s = src[i], d = dst[i];
    int rs = atomicAdd(&g_deg[s], 1);
    int rd = atomicAdd(&g_deg[d], 1);
    g_rank[i] = make_int2(rs, rd);
}

// Exclusive scan of degrees -> rowstart, plus dis.
#define SCAN_T 1024
__global__ void k_scan(int N) {
    __shared__ int sums[SCAN_T];
    int t = threadIdx.x;
    int chunk = (N + SCAN_T - 1) / SCAN_T;
    int beg = t * chunk;
    int end = min(beg + chunk, N);
    int s = 0;
    for (int i = beg; i < end; i++) s += g_deg[i];
    sums[t] = s;
    __syncthreads();
    if (t == 0) {
        int run = 0;
        for (int u = 0; u < SCAN_T; u++) {
            int v = sums[u];
            sums[u] = run;       // exclusive prefix
            run += v;
        }
        g_rowstart[N] = run;     // total = 2E
    }
    __syncthreads();
    int run = sums[t];
    for (int i = beg; i < end; i++) {
        int d = g_deg[i];
        g_rowstart[i] = run;
        g_dis[i] = rsqrtf((float)d + 1.0f);
        run += d;
    }
}

// CSR fill, atomic-free: slot = rowstart[node] + precomputed rank.
__global__ void k_fill_adj(const int* __restrict__ src,
                           const int* __restrict__ dst, int E) {
    int i = blockIdx.x * blockDim.x + threadIdx.x;
    if (i >= E) return;
    int s = src[i], d = dst[i];
    int2 r = g_rank[i];
    float c = g_dis[s] * g_dis[d];
    long long cbits = ((long long)__float_as_int(c)) << 32;
    g_adjc[g_rowstart[s] + r.x] = cbits | (unsigned int)d;
    g_adjc[g_rowstart[d] + r.y] = cbits | (unsigned int)s;
}

// ---------------------------------------------------------------------------
// Fused: g_hw = relu(x @ W_in + b_in) @ W1.  (h never hits global memory.)
// Block tile 128 rows, 128 threads, 8x8 register tile, BK=16.
__global__ void k_gemm_fused(const float* __restrict__ x,
                             const float* __restrict__ W,
                             const float* __restrict__ bias,
                             const float* __restrict__ W1, int N) {
    __shared__ float As[16][128];
    __shared__ float Ws[16][64];
    __shared__ float Hs[64][128];   // transposed h tile: Hs[feat][row]
    int t  = threadIdx.x;
    int tr = t >> 3;                // 0..15
    int tc = t & 7;                 // 0..7
    int row0 = blockIdx.x * 128;

    float acc[8][8];
    #pragma unroll
    for (int i = 0; i < 8; i++)
        #pragma unroll
        for (int j = 0; j < 8; j++) acc[i][j] = 0.0f;

    // ---- GEMM 1: x[128 x 192] @ W_in[192 x 64] ----
    for (int kt = 0; kt < DIN; kt += 16) {
        {
            int gr = row0 + t;
            float4 v0, v1, v2, v3;
            if (gr < N) {
                const float4* Ar = (const float4*)(x + (long)gr * DIN + kt);
                v0 = Ar[0]; v1 = Ar[1]; v2 = Ar[2]; v3 = Ar[3];
            } else {
                v0 = make_float4(0.f,0.f,0.f,0.f); v1 = v0; v2 = v0; v3 = v0;
            }
            As[ 0][t] = v0.x; As[ 1][t] = v0.y; As[ 2][t] = v0.z; As[ 3][t] = v0.w;
            As[ 4][t] = v1.x; As[ 5][t] = v1.y; As[ 6][t] = v1.z; As[ 7][t] = v1.w;
            As[ 8][t] = v2.x; As[ 9][t] = v2.y; As[10][t] = v2.z; As[11][t] = v2.w;
            As[12][t] = v3.x; As[13][t] = v3.y; As[14][t] = v3.z; As[15][t] = v3.w;
        }
        {
            const float4* Wg = (const float4*)(W + kt * 64);
            ((float4*)Ws)[t]       = Wg[t];
            ((float4*)Ws)[t + 128] = Wg[t + 128];
        }
        __syncthreads();
        #pragma unroll
        for (int k = 0; k < 16; k++) {
            float4 a0 = *(const float4*)&As[k][tr * 8];
            float4 a1 = *(const float4*)&As[k][tr * 8 + 4];
            float4 b0 = *(const float4*)&Ws[k][tc * 8];
            float4 b1 = *(const float4*)&Ws[k][tc * 8 + 4];
            float a[8], b[8];
            a[0]=a0.x; a[1]=a0.y; a[2]=a0.z; a[3]=a0.w;
            a[4]=a1.x; a[5]=a1.y; a[6]=a1.z; a[7]=a1.w;
            b[0]=b0.x; b[1]=b0.y; b[2]=b0.z; b[3]=b0.w;
            b[4]=b1.x; b[5]=b1.y; b[6]=b1.z; b[7]=b1.w;
            #pragma unroll
            for (int i = 0; i < 8; i++)
                #pragma unroll
                for (int j = 0; j < 8; j++)
                    acc[i][j] = fmaf(a[i], b[j], acc[i][j]);
        }
        __syncthreads();
    }

    // Epilogue 1: h = relu(acc + bias), transposed into Hs[feat][row].
    {
        float4 bb0 = ((const float4*)bias)[tc * 2];
        float4 bb1 = ((const float4*)bias)[tc * 2 + 1];
        float bv[8];
        bv[0]=bb0.x; bv[1]=bb0.y; bv[2]=bb0.z; bv[3]=bb0.w;
        bv[4]=bb1.x; bv[5]=bb1.y; bv[6]=bb1.z; bv[7]=bb1.w;
        #pragma unroll
        for (int i = 0; i < 8; i++)
            #pragma unroll
            for (int j = 0; j < 8; j++)
                Hs[tc * 8 + j][tr * 8 + i] = fmaxf(acc[i][j] + bv[j], 0.0f);
    }
    __syncthreads();

    // ---- GEMM 2: h[128 x 64] @ W1[64 x 64] ----
    #pragma unroll
    for (int i = 0; i < 8; i++)
        #pragma unroll
        for (int j = 0; j < 8; j++) acc[i][j] = 0.0f;

    for (int kt = 0; kt < HH; kt += 16) {
        {
            const float4* Wg = (const float4*)(W1 + kt * 64);
            ((float4*)Ws)[t]       = Wg[t];
            ((float4*)Ws)[t + 128] = Wg[t + 128];
        }
        __syncthreads();
        #pragma unroll
        for (int k = 0; k < 16; k++) {
            float4 a0 = *(const float4*)&Hs[kt + k][tr * 8];
            float4 a1 = *(const float4*)&Hs[kt + k][tr * 8 + 4];
            float4 b0 = *(const float4*)&Ws[k][tc * 8];
            float4 b1 = *(const float4*)&Ws[k][tc * 8 + 4];
            float a[8], b[8];
            a[0]=a0.x; a[1]=a0.y; a[2]=a0.z; a[3]=a0.w;
            a[4]=a1.x; a[5]=a1.y; a[6]=a1.z; a[7]=a1.w;
            b[0]=b0.x; b[1]=b0.y; b[2]=b0.z; b[3]=b0.w;
            b[4]=b1.x; b[5]=b1.y; b[6]=b1.z; b[7]=b1.w;
            #pragma unroll
            for (int i = 0; i < 8; i++)
                #pragma unroll
                for (int j = 0; j < 8; j++)
                    acc[i][j] = fmaf(a[i], b[j], acc[i][j]);
        }
        __syncthreads();
    }

    #pragma unroll
    for (int i = 0; i < 8; i++) {
        int gr = row0 + tr * 8 + i;
        if (gr < N) {
            float4 o0, o1;
            o0.x = acc[i][0]; o0.y = acc[i][1]; o0.z = acc[i][2]; o0.w = acc[i][3];
            o1.x = acc[i][4]; o1.y = acc[i][5]; o1.z = acc[i][6]; o1.w = acc[i][7];
            float4* Cr = (float4*)(g_hw + (long)gr * 64 + tc * 8);
            Cr[0] = o0;
            Cr[1] = o1;
        }
    }
}

// g_hw = g_h @ W2 (64x64). Same register-tiled structure.
__global__ void k_gemm2(const float* __restrict__ W, int N) {
    __shared__ float As[16][128];
    __shared__ float Ws[16][64];
    int t  = threadIdx.x;
    int tr = t >> 3;
    int tc = t & 7;
    int row0 = blockIdx.x * 128;

    float acc[8][8];
    #pragma unroll
    for (int i = 0; i < 8; i++)
        #pragma unroll
        for (int j = 0; j < 8; j++) acc[i][j] = 0.0f;

    for (int kt = 0; kt < HH; kt += 16) {
        {
            int gr = row0 + t;
            float4 v0, v1, v2, v3;
            if (gr < N) {
                const float4* Ar = (const float4*)(g_h + (long)gr * HH + kt);
                v0 = Ar[0]; v1 = Ar[1]; v2 = Ar[2]; v3 = Ar[3];
            } else {
                v0 = make_float4(0.f,0.f,0.f,0.f); v1 = v0; v2 = v0; v3 = v0;
            }
            As[ 0][t] = v0.x; As[ 1][t] = v0.y; As[ 2][t] = v0.z; As[ 3][t] = v0.w;
            As[ 4][t] = v1.x; As[ 5][t] = v1.y; As[ 6][t] = v1.z; As[ 7][t] = v1.w;
            As[ 8][t] = v2.x; As[ 9][t] = v2.y; As[10][t] = v2.z; As[11][t] = v2.w;
            As[12][t] = v3.x; As[13][t] = v3.y; As[14][t] = v3.z; As[15][t] = v3.w;
        }
        {
            const float4* Wg = (const float4*)(W + kt * 64);
            ((float4*)Ws)[t]       = Wg[t];
            ((float4*)Ws)[t + 128] = Wg[t + 128];
        }
        __syncthreads();
        #pragma unroll
        for (int k = 0; k < 16; k++) {
            float4 a0 = *(const float4*)&As[k][tr * 8];
            float4 a1 = *(const float4*)&As[k][tr * 8 + 4];
            float4 b0 = *(const float4*)&Ws[k][tc * 8];
            float4 b1 = *(const float4*)&Ws[k][tc * 8 + 4];
            float a[8], b[8];
            a[0]=a0.x; a[1]=a0.y; a[2]=a0.z; a[3]=a0.w;
            a[4]=a1.x; a[5]=a1.y; a[6]=a1.z; a[7]=a1.w;
            b[0]=b0.x; b[1]=b0.y; b[2]=b0.z; b[3]=b0.w;
            b[4]=b1.x; b[5]=b1.y; b[6]=b1.z; b[7]=b1.w;
            #pragma unroll
            for (int i = 0; i < 8; i++)
                #pragma unroll
                for (int j = 0; j < 8; j++)
                    acc[i][j] = fmaf(a[i], b[j], acc[i][j]);
        }
        __syncthreads();
    }

    #pragma unroll
    for (int i = 0; i < 8; i++) {
        int gr = row0 + tr * 8 + i;
        if (gr < N) {
            float4 o0, o1;
            o0.x = acc[i][0]; o0.y = acc[i][1]; o0.z = acc[i][2]; o0.w = acc[i][3];
            o1.x = acc[i][4]; o1.y = acc[i][5]; o1.z = acc[i][6]; o1.w = acc[i][7];
            float4* Cr = (float4*)(g_hw + (long)gr * 64 + tc * 8);
            Cr[0] = o0;
            Cr[1] = o1;
        }
    }
}

// ---------------------------------------------------------------------------
// Pull-based aggregation: 16 lanes per node. Warp-cooperative adjacency:
// each 16-lane group loads 16 (nbr,coef) entries coalesced (one long long
// per lane), then shfl-broadcasts entry j to all lanes. Padding lanes carry
// (nb=0, c=0) -> gathers hit node 0's L1-hot row and contribute zero.
// POOL=false: g_h[n] = relu(agg + b)
// POOL=true : red_add relu(agg + b) into g_pool[batch[n]] (skip g_h).
template<bool POOL>
__global__ void k_aggregate(const float* __restrict__ b,
                            const int* __restrict__ batch, int N) {
    int n = blockIdx.x * 16 + (threadIdx.x >> 4);
    int lane = threadIdx.x & 31;
    int grp = lane >> 4;          // node group within warp (0/1)
    int q = lane & 15;            // feature slot (4 floats each)
    if (n >= N) return;

    const float4* hw4 = (const float4*)g_hw;
    float dn = g_dis[n];
    float dn2 = dn * dn;
    float4 acc = hw4[n * 16 + q];
    acc.x *= dn2; acc.y *= dn2; acc.z *= dn2; acc.w *= dn2;

    int s = g_rowstart[n];
    int e = g_rowstart[n + 1];
    for (int base = s; base < e; base += 16) {
        int idx = base + q;
        long long av = (idx < e) ? g_adjc[idx] : 0LL;
        #pragma unroll
        for (int j = 0; j < 16; j++) {
            long long aj = __shfl_sync(0xffffffffu, av, grp * 16 + j, 32);
            int nb  = (int)(aj & 0xffffffffLL);
            float c = __int_as_float((int)(aj >> 32));
            float4 v = hw4[nb * 16 + q];
            acc.x = fmaf(v.x, c, acc.x);
            acc.y = fmaf(v.y, c, acc.y);
            acc.z = fmaf(v.z, c, acc.z);
            acc.w = fmaf(v.w, c, acc.w);
        }
    }

    float4 bb = ((const float4*)b)[q];
    acc.x = fmaxf(acc.x + bb.x, 0.0f);
    acc.y = fmaxf(acc.y + bb.y, 0.0f);
    acc.z = fmaxf(acc.z + bb.z, 0.0f);
    acc.w = fmaxf(acc.w + bb.w, 0.0f);

    if (POOL) {
        int g = batch[n];
        red_add_v4(&((float4*)g_pool)[g * 16 + q], acc.x, acc.y, acc.z, acc.w);
        if (q == 0) atomicAdd(&g_cnt[g], 1.0f);
    } else {
        ((float4*)g_h)[n * 16 + q] = acc;
    }
}

// ---------------------------------------------------------------------------
__global__ void k_head(const float* __restrict__ Wf1,
                       const float* __restrict__ bf1,
                       const float* __restrict__ Wf2,
                       const float* __restrict__ bf2,
                       float* __restrict__ out) {
    __shared__ float W1s[HH * DOUTT];
    __shared__ float b1s[DOUTT];
    __shared__ float W2s[DOUTT * CC];
    __shared__ float b2s[CC];
    for (int i = threadIdx.x; i < HH * DOUTT; i += blockDim.x) W1s[i] = Wf1[i];
    if (threadIdx.x < DOUTT) b1s[threadIdx.x] = bf1[threadIdx.x];
    if (threadIdx.x < DOUTT * CC) W2s[threadIdx.x] = Wf2[threadIdx.x];
    if (threadIdx.x < CC) b2s[threadIdx.x] = bf2[threadIdx.x];
    __syncthreads();
    int g = threadIdx.x;
    if (g >= GG) return;
    float inv = 1.0f / fmaxf(g_cnt[g], 1.0f);
    float m[HH];
    #pragma unroll
    for (int k = 0; k < HH; k++) m[k] = g_pool[g * HH + k] * inv;
    float o0 = b2s[0], o1 = b2s[1];
    #pragma unroll
    for (int j = 0; j < DOUTT; j++) {
        float a = b1s[j];
        #pragma unroll
        for (int k = 0; k < HH; k++) a = fmaf(m[k], W1s[k * DOUTT + j], a);
        a = fmaxf(a, 0.0f);
        o0 = fmaf(a, W2s[j * CC + 0], o0);
        o1 = fmaf(a, W2s[j * CC + 1], o1);
    }
    float mx = fmaxf(o0, o1);
    float l = mx + logf(expf(o0 - mx) + expf(o1 - mx));
    out[g * CC + 0] = o0 - l;
    out[g * CC + 1] = o1 - l;
}

// ---------------------------------------------------------------------------
extern "C" void kernel_launch(void* const* d_in, const int* in_sizes, int n_in,
                              void* d_out, int out_size) {
    const float* x     = (const float*)d_in[0];
    const int*   ei    = (const int*)d_in[1];
    const int*   batch = (const int*)d_in[2];
    int idx = (n_in >= 14 && in_sizes[3] == 1) ? 4 : 3;
    const float* W_in = (const float*)d_in[idx++];
    const float* b_in = (const float*)d_in[idx++];
    const float* W1   = (const float*)d_in[idx++];
    const float* b1   = (const float*)d_in[idx++];
    const float* W2   = (const float*)d_in[idx++];
    const float* b2   = (const float*)d_in[idx++];
    const float* Wf1  = (const float*)d_in[idx++];
    const float* bf1  = (const float*)d_in[idx++];
    const float* Wf2  = (const float*)d_in[idx++];
    const float* bf2  = (const float*)d_in[idx++];

    int N = in_sizes[0] / DIN;
    int E = in_sizes[1] / 2;
    const int* src = ei;
    const int* dst = ei + E;

    // One-time stream/event setup.
    static cudaStream_t sB = nullptr;
    static cudaEvent_t evFork = nullptr, evJoin = nullptr;
    if (sB == nullptr) {
        cudaStreamCreateWithFlags(&sB, cudaStreamNonBlocking);
        cudaEventCreateWithFlags(&evFork, cudaEventDisableTiming);
        cudaEventCreateWithFlags(&evJoin, cudaEventDisableTiming);
    }

    // Fork: CSR build on side stream, GEMM chain on main stream.
    cudaEventRecord(evFork, 0);
    cudaStreamWaitEvent(sB, evFork, 0);

    // --- side stream: CSR build ---
    k_init<<<(NN + 255) / 256, 256, 0, sB>>>();
    k_degree<<<(E + 255) / 256, 256, 0, sB>>>(src, dst, E);
    k_scan<<<1, SCAN_T, 0, sB>>>(N);
    k_fill_adj<<<(E + 255) / 256, 256, 0, sB>>>(src, dst, E);
    cudaEventRecord(evJoin, sB);

    int gblocks = (N + 127) / 128;

    // --- main stream: g_hw = relu(x @ W_in + b_in) @ W1 ---
    k_gemm_fused<<<gblocks, 128>>>(x, W_in, b_in, W1, N);

    // Join: aggregation needs both CSR and g_hw.
    cudaStreamWaitEvent(0, evJoin, 0);

    // conv 1 aggregate -> g_h
    k_aggregate<false><<<(N + 15) / 16, 256>>>(b1, nullptr, N);

    // conv 2
    k_gemm2<<<gblocks, 128>>>(W2, N);
    // conv 2 aggregate fused with mean-pool accumulation
    k_aggregate<true><<<(N + 15) / 16, 256>>>(b2, batch, N);

    // head
    k_head<<<1, 256>>>(Wf1, bf1, Wf2, bf2, (float*)d_out);
}

// round 9
// speedup vs baseline: 1.4816x; 1.1079x over previous
#include <cuda_runtime.h>
#include <cuda_fp16.h>
#include <math.h>

// Problem constants (fixed by the dataset)
#define NN    100000
#define EMAX  1600000
#define E2MAX 3200000   // 2 * EMAX
#define DIN   192
#define HH    64
#define DOUTT 32
#define CC    2
#define GG    256

typedef unsigned long long u64;

// Scratch (static device arrays -- no allocation allowed)
__device__ __align__(16) float  g_h  [NN * HH];   // node features (fp32)
__device__ __align__(16) __half g_hwh[NN * HH];   // h @ W, fp16 gather payload
__device__ float g_dis[NN];          // deg^{-1/2}
__device__ int   g_deg[NN];          // degree (no self-loop)
__device__ int   g_rowstart[NN + 1]; // CSR row offsets
__device__ __align__(16) int2 g_rank[EMAX];  // (rank in src list, rank in dst list)
__device__ __align__(16) int2 g_adjc[E2MAX]; // (neighbor, coef bits)
__device__ __align__(16) float g_pool[GG * HH];
__device__ float g_cnt [GG];

__device__ __forceinline__ void red_add_v4(float4* addr, float a, float b,
                                           float c, float d) {
    asm volatile("red.global.add.v4.f32 [%0], {%1, %2, %3, %4};"
                 :: "l"(addr), "f"(a), "f"(b), "f"(c), "f"(d)
                 : "memory");
}

// ---- packed f32x2 helpers (sm_100+) ---------------------------------------
__device__ __forceinline__ u64 pk2(float x, float y) {
    u64 r;
    asm("mov.b64 %0, {%1, %2};" : "=l"(r) : "f"(x), "f"(y));
    return r;
}
__device__ __forceinline__ void upk2(u64 v, float* x, float* y) {
    asm("mov.b64 {%0, %1}, %2;" : "=f"(*x), "=f"(*y) : "l"(v));
}
__device__ __forceinline__ u64 fma2(u64 a, u64 b, u64 c) {
    u64 d;
    asm("fma.rn.f32x2 %0, %1, %2, %3;" : "=l"(d) : "l"(a), "l"(b), "l"(c));
    return d;
}

// ---------------------------------------------------------------------------
__global__ void k_init() {
    int i = blockIdx.x * blockDim.x + threadIdx.x;
    if (i < NN) g_deg[i] = 0;
    if (i < GG * HH) g_pool[i] = 0.0f;
    if (i < GG) g_cnt[i] = 0.0f;
}

// Degree histogram; keep the returned rank so the fill pass needs no atomics.
__global__ void k_degree(const int* __restrict__ src,
                         const int* __restrict__ dst, int E) {
    int i = blockIdx.x * blockDim.x + threadIdx.x;
    if (i >= E) return;
    int s = src[i], d = dst[i];
    int rs = atomicAdd(&g_deg[s], 1);
    int rd = atomicAdd(&g_deg[d], 1);
    g_rank[i] = make_int2(rs, rd);
}

// Exclusive scan of degrees -> rowstart, plus dis.
#define SCAN_T 1024
__global__ void k_scan(int N) {
    __shared__ int sums[SCAN_T];
    int t = threadIdx.x;
    int chunk = (N + SCAN_T - 1) / SCAN_T;
    int beg = t * chunk;
    int end = min(beg + chunk, N);
    int s = 0;
    for (int i = beg; i < end; i++) s += g_deg[i];
    sums[t] = s;
    __syncthreads();
    if (t == 0) {
        int run = 0;
        for (int u = 0; u < SCAN_T; u++) {
            int v = sums[u];
            sums[u] = run;       // exclusive prefix
            run += v;
        }
        g_rowstart[N] = run;     // total = 2E
    }
    __syncthreads();
    int run = sums[t];
    for (int i = beg; i < end; i++) {
        int d = g_deg[i];
        g_rowstart[i] = run;
        g_dis[i] = rsqrtf((float)d + 1.0f);
        run += d;
    }
}

// CSR fill, atomic-free: slot = rowstart[node] + precomputed rank.
__global__ void k_fill_adj(const int* __restrict__ src,
                           const int* __restrict__ dst, int E) {
    int i = blockIdx.x * blockDim.x + threadIdx.x;
    if (i >= E) return;
    int s = src[i], d = dst[i];
    int2 r = g_rank[i];
    float c = g_dis[s] * g_dis[d];
    int ci = __float_as_int(c);
    g_adjc[g_rowstart[s] + r.x] = make_int2(d, ci);
    g_adjc[g_rowstart[d] + r.y] = make_int2(s, ci);
}

// ---------------------------------------------------------------------------
// Write one row-chunk of 8 fp32 values as 8 fp16 (one uint4) to g_hwh.
__device__ __forceinline__ void store_h8(int row, int tc, const float* v) {
    __half2 h0 = __floats2half2_rn(v[0], v[1]);
    __half2 h1 = __floats2half2_rn(v[2], v[3]);
    __half2 h2 = __floats2half2_rn(v[4], v[5]);
    __half2 h3 = __floats2half2_rn(v[6], v[7]);
    uint4 u;
    u.x = *(unsigned*)&h0;
    u.y = *(unsigned*)&h1;
    u.z = *(unsigned*)&h2;
    u.w = *(unsigned*)&h3;
    ((uint4*)g_hwh)[row * 8 + tc] = u;
}

// ---------------------------------------------------------------------------
// Fused: g_hwh = fp16( relu(x @ W_in + b_in) @ W1 ).  h never hits gmem.
// Block tile 128 rows, 128 threads, 8x8 register tile, BK=16, f32x2 FMA.
__global__ void k_gemm_fused(const float* __restrict__ x,
                             const float* __restrict__ W,
                             const float* __restrict__ bias,
                             const float* __restrict__ W1, int N) {
    __shared__ __align__(16) float As[16][128];
    __shared__ __align__(16) float Ws[16][64];
    __shared__ __align__(16) float Hs[64][128];   // transposed h: Hs[feat][row]
    int t  = threadIdx.x;
    int tr = t >> 3;                // 0..15
    int tc = t & 7;                 // 0..7
    int row0 = blockIdx.x * 128;

    u64 acc2[8][4];
    #pragma unroll
    for (int i = 0; i < 8; i++)
        #pragma unroll
        for (int j = 0; j < 4; j++) acc2[i][j] = 0ULL;

    // ---- GEMM 1: x[128 x 192] @ W_in[192 x 64] ----
    for (int kt = 0; kt < DIN; kt += 16) {
        {
            int gr = row0 + t;
            float4 v0, v1, v2, v3;
            if (gr < N) {
                const float4* Ar = (const float4*)(x + (long)gr * DIN + kt);
                v0 = Ar[0]; v1 = Ar[1]; v2 = Ar[2]; v3 = Ar[3];
            } else {
                v0 = make_float4(0.f,0.f,0.f,0.f); v1 = v0; v2 = v0; v3 = v0;
            }
            As[ 0][t] = v0.x; As[ 1][t] = v0.y; As[ 2][t] = v0.z; As[ 3][t] = v0.w;
            As[ 4][t] = v1.x; As[ 5][t] = v1.y; As[ 6][t] = v1.z; As[ 7][t] = v1.w;
            As[ 8][t] = v2.x; As[ 9][t] = v2.y; As[10][t] = v2.z; As[11][t] = v2.w;
            As[12][t] = v3.x; As[13][t] = v3.y; As[14][t] = v3.z; As[15][t] = v3.w;
        }
        {
            const float4* Wg = (const float4*)(W + kt * 64);
            ((float4*)Ws)[t]       = Wg[t];
            ((float4*)Ws)[t + 128] = Wg[t + 128];
        }
        __syncthreads();
        #pragma unroll
        for (int k = 0; k < 16; k++) {
            float4 a0 = *(const float4*)&As[k][tr * 8];
            float4 a1 = *(const float4*)&As[k][tr * 8 + 4];
            const u64* bw = (const u64*)&Ws[k][tc * 8];
            u64 b0 = bw[0], b1 = bw[1], b2 = bw[2], b3 = bw[3];
            float a[8];
            a[0]=a0.x; a[1]=a0.y; a[2]=a0.z; a[3]=a0.w;
            a[4]=a1.x; a[5]=a1.y; a[6]=a1.z; a[7]=a1.w;
            #pragma unroll
            for (int i = 0; i < 8; i++) {
                u64 aa = pk2(a[i], a[i]);
                acc2[i][0] = fma2(aa, b0, acc2[i][0]);
                acc2[i][1] = fma2(aa, b1, acc2[i][1]);
                acc2[i][2] = fma2(aa, b2, acc2[i][2]);
                acc2[i][3] = fma2(aa, b3, acc2[i][3]);
            }
        }
        __syncthreads();
    }

    // Epilogue 1: h = relu(acc + bias), transposed into Hs[feat][row].
    {
        float4 bb0 = ((const float4*)bias)[tc * 2];
        float4 bb1 = ((const float4*)bias)[tc * 2 + 1];
        float bv[8];
        bv[0]=bb0.x; bv[1]=bb0.y; bv[2]=bb0.z; bv[3]=bb0.w;
        bv[4]=bb1.x; bv[5]=bb1.y; bv[6]=bb1.z; bv[7]=bb1.w;
        #pragma unroll
        for (int i = 0; i < 8; i++) {
            float o[8];
            upk2(acc2[i][0], &o[0], &o[1]);
            upk2(acc2[i][1], &o[2], &o[3]);
            upk2(acc2[i][2], &o[4], &o[5]);
            upk2(acc2[i][3], &o[6], &o[7]);
            #pragma unroll
            for (int j = 0; j < 8; j++)
                Hs[tc * 8 + j][tr * 8 + i] = fmaxf(o[j] + bv[j], 0.0f);
        }
    }
    __syncthreads();

    // ---- GEMM 2: h[128 x 64] @ W1[64 x 64] ----
    #pragma unroll
    for (int i = 0; i < 8; i++)
        #pragma unroll
        for (int j = 0; j < 4; j++) acc2[i][j] = 0ULL;

    for (int kt = 0; kt < HH; kt += 16) {
        {
            const float4* Wg = (const float4*)(W1 + kt * 64);
            ((float4*)Ws)[t]       = Wg[t];
            ((float4*)Ws)[t + 128] = Wg[t + 128];
        }
        __syncthreads();
        #pragma unroll
        for (int k = 0; k < 16; k++) {
            float4 a0 = *(const float4*)&Hs[kt + k][tr * 8];
            float4 a1 = *(const float4*)&Hs[kt + k][tr * 8 + 4];
            const u64* bw = (const u64*)&Ws[k][tc * 8];
            u64 b0 = bw[0], b1 = bw[1], b2 = bw[2], b3 = bw[3];
            float a[8];
            a[0]=a0.x; a[1]=a0.y; a[2]=a0.z; a[3]=a0.w;
            a[4]=a1.x; a[5]=a1.y; a[6]=a1.z; a[7]=a1.w;
            #pragma unroll
            for (int i = 0; i < 8; i++) {
                u64 aa = pk2(a[i], a[i]);
                acc2[i][0] = fma2(aa, b0, acc2[i][0]);
                acc2[i][1] = fma2(aa, b1, acc2[i][1]);
                acc2[i][2] = fma2(aa, b2, acc2[i][2]);
                acc2[i][3] = fma2(aa, b3, acc2[i][3]);
            }
        }
        __syncthreads();
    }

    #pragma unroll
    for (int i = 0; i < 8; i++) {
        int gr = row0 + tr * 8 + i;
        if (gr < N) {
            float o[8];
            upk2(acc2[i][0], &o[0], &o[1]);
            upk2(acc2[i][1], &o[2], &o[3]);
            upk2(acc2[i][2], &o[4], &o[5]);
            upk2(acc2[i][3], &o[6], &o[7]);
            store_h8(gr, tc, o);
        }
    }
}

// g_hwh = fp16( g_h @ W2 ). Same register-tiled structure, f32x2 FMA.
__global__ void k_gemm2(const float* __restrict__ W, int N) {
    __shared__ __align__(16) float As[16][128];
    __shared__ __align__(16) float Ws[16][64];
    int t  = threadIdx.x;
    int tr = t >> 3;
    int tc = t & 7;
    int row0 = blockIdx.x * 128;

    u64 acc2[8][4];
    #pragma unroll
    for (int i = 0; i < 8; i++)
        #pragma unroll
        for (int j = 0; j < 4; j++) acc2[i][j] = 0ULL;

    for (int kt = 0; kt < HH; kt += 16) {
        {
            int gr = row0 + t;
            float4 v0, v1, v2, v3;
            if (gr < N) {
                const float4* Ar = (const float4*)(g_h + (long)gr * HH + kt);
                v0 = Ar[0]; v1 = Ar[1]; v2 = Ar[2]; v3 = Ar[3];
            } else {
                v0 = make_float4(0.f,0.f,0.f,0.f); v1 = v0; v2 = v0; v3 = v0;
            }
            As[ 0][t] = v0.x; As[ 1][t] = v0.y; As[ 2][t] = v0.z; As[ 3][t] = v0.w;
            As[ 4][t] = v1.x; As[ 5][t] = v1.y; As[ 6][t] = v1.z; As[ 7][t] = v1.w;
            As[ 8][t] = v2.x; As[ 9][t] = v2.y; As[10][t] = v2.z; As[11][t] = v2.w;
            As[12][t] = v3.x; As[13][t] = v3.y; As[14][t] = v3.z; As[15][t] = v3.w;
        }
        {
            const float4* Wg = (const float4*)(W + kt * 64);
            ((float4*)Ws)[t]       = Wg[t];
            ((float4*)Ws)[t + 128] = Wg[t + 128];
        }
        __syncthreads();
        #pragma unroll
        for (int k = 0; k < 16; k++) {
            float4 a0 = *(const float4*)&As[k][tr * 8];
            float4 a1 = *(const float4*)&As[k][tr * 8 + 4];
            const u64* bw = (const u64*)&Ws[k][tc * 8];
            u64 b0 = bw[0], b1 = bw[1], b2 = bw[2], b3 = bw[3];
            float a[8];
            a[0]=a0.x; a[1]=a0.y; a[2]=a0.z; a[3]=a0.w;
            a[4]=a1.x; a[5]=a1.y; a[6]=a1.z; a[7]=a1.w;
            #pragma unroll
            for (int i = 0; i < 8; i++) {
                u64 aa = pk2(a[i], a[i]);
                acc2[i][0] = fma2(aa, b0, acc2[i][0]);
                acc2[i][1] = fma2(aa, b1, acc2[i][1]);
                acc2[i][2] = fma2(aa, b2, acc2[i][2]);
                acc2[i][3] = fma2(aa, b3, acc2[i][3]);
            }
        }
        __syncthreads();
    }

    #pragma unroll
    for (int i = 0; i < 8; i++) {
        int gr = row0 + tr * 8 + i;
        if (gr < N) {
            float o[8];
            upk2(acc2[i][0], &o[0], &o[1]);
            upk2(acc2[i][1], &o[2], &o[3]);
            upk2(acc2[i][2], &o[4], &o[5]);
            upk2(acc2[i][3], &o[6], &o[7]);
            store_h8(gr, tc, o);
        }
    }
}

// ---------------------------------------------------------------------------
// Pull-based aggregation on fp16 payload, R5 shape: 16 lanes per node, each
// lane owns 4 features (uint2 = 8B per neighbor), unroll x8 for MLP.
// POOL=false: g_h[n] = relu(agg + b)   (fp32)
// POOL=true : red_add relu(agg + b) into g_pool[batch[n]].
__device__ __forceinline__ void acc_h4(float4& acc, uint2 u, float c) {
    __half2 h0 = *(__half2*)&u.x;
    __half2 h1 = *(__half2*)&u.y;
    float2 f0 = __half22float2(h0);
    float2 f1 = __half22float2(h1);
    acc.x = fmaf(f0.x, c, acc.x);
    acc.y = fmaf(f0.y, c, acc.y);
    acc.z = fmaf(f1.x, c, acc.z);
    acc.w = fmaf(f1.y, c, acc.w);
}

template<bool POOL>
__global__ void k_aggregate(const float* __restrict__ b,
                            const int* __restrict__ batch, int N) {
    int n = blockIdx.x * 16 + (threadIdx.x >> 4);
    int q = threadIdx.x & 15;           // feature slot: 4 halfs
    if (n >= N) return;
    const uint2* hwh = (const uint2*)g_hwh;
    float dn = g_dis[n];
    float dn2 = dn * dn;
    float4 acc = make_float4(0.f, 0.f, 0.f, 0.f);
    acc_h4(acc, hwh[n * 16 + q], dn2);  // self-loop term

    int s = g_rowstart[n];
    int e = g_rowstart[n + 1];
    int i = s;
    for (; i + 8 <= e; i += 8) {
        int2 a0 = g_adjc[i];
        int2 a1 = g_adjc[i + 1];
        int2 a2 = g_adjc[i + 2];
        int2 a3 = g_adjc[i + 3];
        int2 a4 = g_adjc[i + 4];
        int2 a5 = g_adjc[i + 5];
        int2 a6 = g_adjc[i + 6];
        int2 a7 = g_adjc[i + 7];
        uint2 u0 = hwh[a0.x * 16 + q];
        uint2 u1 = hwh[a1.x * 16 + q];
        uint2 u2 = hwh[a2.x * 16 + q];
        uint2 u3 = hwh[a3.x * 16 + q];
        uint2 u4 = hwh[a4.x * 16 + q];
        uint2 u5 = hwh[a5.x * 16 + q];
        uint2 u6 = hwh[a6.x * 16 + q];
        uint2 u7 = hwh[a7.x * 16 + q];
        acc_h4(acc, u0, __int_as_float(a0.y));
        acc_h4(acc, u1, __int_as_float(a1.y));
        acc_h4(acc, u2, __int_as_float(a2.y));
        acc_h4(acc, u3, __int_as_float(a3.y));
        acc_h4(acc, u4, __int_as_float(a4.y));
        acc_h4(acc, u5, __int_as_float(a5.y));
        acc_h4(acc, u6, __int_as_float(a6.y));
        acc_h4(acc, u7, __int_as_float(a7.y));
    }
    for (; i < e; i++) {
        int2 a0 = g_adjc[i];
        uint2 u0 = hwh[a0.x * 16 + q];
        acc_h4(acc, u0, __int_as_float(a0.y));
    }

    float4 bb = ((const float4*)b)[q];
    acc.x = fmaxf(acc.x + bb.x, 0.0f);
    acc.y = fmaxf(acc.y + bb.y, 0.0f);
    acc.z = fmaxf(acc.z + bb.z, 0.0f);
    acc.w = fmaxf(acc.w + bb.w, 0.0f);

    if (POOL) {
        int g = batch[n];
        red_add_v4(&((float4*)g_pool)[g * 16 + q], acc.x, acc.y, acc.z, acc.w);
        if (q == 0) atomicAdd(&g_cnt[g], 1.0f);
    } else {
        ((float4*)g_h)[n * 16 + q] = acc;
    }
}

// ---------------------------------------------------------------------------
__global__ void k_head(const float* __restrict__ Wf1,
                       const float* __restrict__ bf1,
                       const float* __restrict__ Wf2,
                       const float* __restrict__ bf2,
                       float* __restrict__ out) {
    __shared__ float W1s[HH * DOUTT];
    __shared__ float b1s[DOUTT];
    __shared__ float W2s[DOUTT * CC];
    __shared__ float b2s[CC];
    for (int i = threadIdx.x; i < HH * DOUTT; i += blockDim.x) W1s[i] = Wf1[i];
    if (threadIdx.x < DOUTT) b1s[threadIdx.x] = bf1[threadIdx.x];
    if (threadIdx.x < DOUTT * CC) W2s[threadIdx.x] = Wf2[threadIdx.x];
    if (threadIdx.x < CC) b2s[threadIdx.x] = bf2[threadIdx.x];
    __syncthreads();
    int g = threadIdx.x;
    if (g >= GG) return;
    float inv = 1.0f / fmaxf(g_cnt[g], 1.0f);
    float m[HH];
    #pragma unroll
    for (int k = 0; k < HH; k++) m[k] = g_pool[g * HH + k] * inv;
    float o0 = b2s[0], o1 = b2s[1];
    #pragma unroll
    for (int j = 0; j < DOUTT; j++) {
        float a = b1s[j];
        #pragma unroll
        for (int k = 0; k < HH; k++) a = fmaf(m[k], W1s[k * DOUTT + j], a);
        a = fmaxf(a, 0.0f);
        o0 = fmaf(a, W2s[j * CC + 0], o0);
        o1 = fmaf(a, W2s[j * CC + 1], o1);
    }
    float mx = fmaxf(o0, o1);
    float l = mx + logf(expf(o0 - mx) + expf(o1 - mx));
    out[g * CC + 0] = o0 - l;
    out[g * CC + 1] = o1 - l;
}

// ---------------------------------------------------------------------------
extern "C" void kernel_launch(void* const* d_in, const int* in_sizes, int n_in,
                              void* d_out, int out_size) {
    const float* x     = (const float*)d_in[0];
    const int*   ei    = (const int*)d_in[1];
    const int*   batch = (const int*)d_in[2];
    int idx = (n_in >= 14 && in_sizes[3] == 1) ? 4 : 3;
    const float* W_in = (const float*)d_in[idx++];
    const float* b_in = (const float*)d_in[idx++];
    const float* W1   = (const float*)d_in[idx++];
    const float* b1   = (const float*)d_in[idx++];
    const float* W2   = (const float*)d_in[idx++];
    const float* b2   = (const float*)d_in[idx++];
    const float* Wf1  = (const float*)d_in[idx++];
    const float* bf1  = (const float*)d_in[idx++];
    const float* Wf2  = (const float*)d_in[idx++];
    const float* bf2  = (const float*)d_in[idx++];

    int N = in_sizes[0] / DIN;
    int E = in_sizes[1] / 2;
    const int* src = ei;
    const int* dst = ei + E;

    // One-time stream/event setup.
    static cudaStream_t sB = nullptr;
    static cudaEvent_t evFork = nullptr, evJoin = nullptr;
    if (sB == nullptr) {
        cudaStreamCreateWithFlags(&sB, cudaStreamNonBlocking);
        cudaEventCreateWithFlags(&evFork, cudaEventDisableTiming);
        cudaEventCreateWithFlags(&evJoin, cudaEventDisableTiming);
    }

    // Fork: CSR build on side stream, GEMM chain on main stream.
    cudaEventRecord(evFork, 0);
    cudaStreamWaitEvent(sB, evFork, 0);

    // --- side stream: CSR build ---
    k_init<<<(NN + 255) / 256, 256, 0, sB>>>();
    k_degree<<<(E + 255) / 256, 256, 0, sB>>>(src, dst, E);
    k_scan<<<1, SCAN_T, 0, sB>>>(N);
    k_fill_adj<<<(E + 255) / 256, 256, 0, sB>>>(src, dst, E);
    cudaEventRecord(evJoin, sB);

    int gblocks = (N + 127) / 128;

    // --- main stream: g_hwh = fp16( relu(x @ W_in + b_in) @ W1 ) ---
    k_gemm_fused<<<gblocks, 128>>>(x, W_in, b_in, W1, N);

    // Join: aggregation needs both CSR and g_hwh.
    cudaStreamWaitEvent(0, evJoin, 0);

    // conv 1 aggregate -> g_h (fp32)
    k_aggregate<false><<<(N + 15) / 16, 256>>>(b1, nullptr, N);

    // conv 2
    k_gemm2<<<gblocks, 128>>>(W2, N);
    // conv 2 aggregate fused with mean-pool accumulation
    k_aggregate<true><<<(N + 15) / 16, 256>>>(b2, batch, N);

    // head
    k_head<<<1, 256>>>(Wf1, bf1, Wf2, bf2, (float*)d_out);
}